// round 8
// baseline (speedup 1.0000x reference)
#include <cuda_runtime.h>

#define NN 100000
#define EE 1600000
#define EN 1700000   // EE + NN self loops
#define FIN 128
#define HH 64
#define BB 128
#define CC 10
#define NEG_SLOPE 0.2f

#define SCAN_B 512
#define NB_SCAN ((NN + SCAN_B - 1) / SCAN_B)   // 196

// ---------------- scratch (device globals; no runtime allocation) ------------
__device__ float g_h[NN * HH];     // W-transformed features of current layer
__device__ float g_x2[NN * HH];    // layer output -> next layer input
__device__ float g_esrc[NN];
__device__ float g_edst[NN];
__device__ int   g_deg[NN];
__device__ int   g_cursor[NN];
__device__ int   g_rowptr[NN + 1];
__device__ int   g_part[SCAN_B];
__device__ int   g_csr_src[EN];    // src node id per CSR slot (dst-sorted)
__device__ float g_pool[BB * HH];

// edge_index is int32 (JAX x64 disabled -> int64 silently becomes int32)
__device__ __forceinline__ void edge_sd(const int* __restrict__ ei, int i,
                                        int& s, int& d) {
    if (i < EE) { s = ei[i]; d = ei[EE + i]; }
    else        { s = i - EE; d = s; }   // self loops appended
}

// ---------------- CSR build --------------------------------------------------

__global__ void csr_init_kernel() {
    int i = blockIdx.x * blockDim.x + threadIdx.x;
    if (i < NN) g_deg[i] = 0;
}

__global__ void csr_hist_kernel(const int* __restrict__ ei) {
    int i = blockIdx.x * blockDim.x + threadIdx.x;
    if (i >= EN) return;
    int s, d; edge_sd(ei, i, s, d);
    atomicAdd(&g_deg[d], 1);
}

__global__ void scan1_kernel() {
    __shared__ int sm[SCAN_B];
    int t = threadIdx.x;
    int i = blockIdx.x * SCAN_B + t;
    int v = (i < NN) ? g_deg[i] : 0;
    sm[t] = v;
    __syncthreads();
    for (int off = 1; off < SCAN_B; off <<= 1) {
        int x = (t >= off) ? sm[t - off] : 0;
        __syncthreads();
        sm[t] += x;
        __syncthreads();
    }
    if (i < NN) g_rowptr[i] = sm[t] - v;          // exclusive within block
    if (t == SCAN_B - 1) g_part[blockIdx.x] = sm[t];
}

__global__ void scan2_kernel() {
    __shared__ int sm[256];
    int t = threadIdx.x;
    int v = (t < NB_SCAN) ? g_part[t] : 0;
    sm[t] = v;
    __syncthreads();
    for (int off = 1; off < 256; off <<= 1) {
        int x = (t >= off) ? sm[t - off] : 0;
        __syncthreads();
        sm[t] += x;
        __syncthreads();
    }
    if (t < NB_SCAN) g_part[t] = sm[t] - v;       // exclusive
}

__global__ void scan3_kernel() {
    int i = blockIdx.x * blockDim.x + threadIdx.x;
    if (i < NN) {
        int v = g_rowptr[i] + g_part[i / SCAN_B];
        g_rowptr[i] = v;
        g_cursor[i] = v;    // fill cursor starts at row base
    }
    if (i == 0) g_rowptr[NN] = EN;
}

__global__ void csr_fill_kernel(const int* __restrict__ ei) {
    int i = blockIdx.x * blockDim.x + threadIdx.x;
    if (i >= EN) return;
    int s, d; edge_sd(ei, i, s, d);
    int pos = atomicAdd(&g_cursor[d], 1);
    g_csr_src[pos] = s;
}

// ---------------- GEMM: h = in @ W^T, plus e_src/e_dst scores ----------------
// 128 threads/block, 32 nodes/block. Each thread: 4 nodes x 4 channels.
// W in smem as ws[k][c] with XOR quad swizzle for conflict-free LDS.128.
template <int FIN_T, bool FROM_X2>
__global__ void gemm_kernel(const float* __restrict__ in,
                            const float* __restrict__ W,
                            const float* __restrict__ a_src,
                            const float* __restrict__ a_dst) {
    __shared__ __align__(16) float ws[FIN_T * 64];
    __shared__ __align__(16) float xs[32][FIN_T];
    int tid = threadIdx.x;
    int c4 = tid & 15;       // channel quad id (channels c4*4 .. c4*4+3)
    int ng = tid >> 4;       // node group (4 nodes each)
    int base = blockIdx.x * 32;
    const float* srcp = FROM_X2 ? g_x2 : in;

    // load W coalesced, store swizzled: ws[k*64 + ((c/4 + k)&15)*4 + c%4]
    for (int idx = tid; idx < 64 * FIN_T; idx += 128) {
        int c = idx / FIN_T, k = idx - c * FIN_T;
        int q = c >> 2, r = c & 3;
        ws[k * 64 + (((q + k) & 15) << 2) + r] = W[idx];
    }
    // load x rows coalesced (float4)
    for (int idx = tid; idx < 32 * (FIN_T / 4); idx += 128) {
        int n = idx / (FIN_T / 4), kq = idx - n * (FIN_T / 4);
        ((float4*)xs[n])[kq] =
            ((const float4*)&srcp[(size_t)(base + n) * FIN_T])[kq];
    }
    __syncthreads();

    float4 acc0 = {0,0,0,0}, acc1 = {0,0,0,0}, acc2 = {0,0,0,0}, acc3 = {0,0,0,0};
    int ns = ng * 4;
#pragma unroll 4
    for (int k = 0; k < FIN_T; k += 4) {
        float4 x0 = *(const float4*)&xs[ns + 0][k];
        float4 x1 = *(const float4*)&xs[ns + 1][k];
        float4 x2 = *(const float4*)&xs[ns + 2][k];
        float4 x3 = *(const float4*)&xs[ns + 3][k];
        float4 w0 = *(const float4*)&ws[(k + 0) * 64 + (((c4 + k + 0) & 15) << 2)];
        float4 w1 = *(const float4*)&ws[(k + 1) * 64 + (((c4 + k + 1) & 15) << 2)];
        float4 w2 = *(const float4*)&ws[(k + 2) * 64 + (((c4 + k + 2) & 15) << 2)];
        float4 w3 = *(const float4*)&ws[(k + 3) * 64 + (((c4 + k + 3) & 15) << 2)];
#define FMA4(A, xv) \
        A.x += xv.x*w0.x + xv.y*w1.x + xv.z*w2.x + xv.w*w3.x; \
        A.y += xv.x*w0.y + xv.y*w1.y + xv.z*w2.y + xv.w*w3.y; \
        A.z += xv.x*w0.z + xv.y*w1.z + xv.z*w2.z + xv.w*w3.z; \
        A.w += xv.x*w0.w + xv.y*w1.w + xv.z*w2.w + xv.w*w3.w;
        FMA4(acc0, x0) FMA4(acc1, x1) FMA4(acc2, x2) FMA4(acc3, x3)
#undef FMA4
    }

    // write h (float4 per node, coalesced across the 16-lane half-warp)
    float4 accs[4] = {acc0, acc1, acc2, acc3};
#pragma unroll
    for (int i = 0; i < 4; i++)
        *(float4*)&g_h[(size_t)(base + ns + i) * HH + c4 * 4] = accs[i];

    // per-node scores: dot over this thread's 4 channels, reduce over 16 lanes
    float4 as4 = *(const float4*)&a_src[c4 * 4];
    float4 ad4 = *(const float4*)&a_dst[c4 * 4];
#pragma unroll
    for (int i = 0; i < 4; i++) {
        float4 a = accs[i];
        float vs = a.x * as4.x + a.y * as4.y + a.z * as4.z + a.w * as4.w;
        float vd = a.x * ad4.x + a.y * ad4.y + a.z * ad4.z + a.w * ad4.w;
#pragma unroll
        for (int off = 8; off; off >>= 1) {
            vs += __shfl_down_sync(0xffffffffu, vs, off, 16);
            vd += __shfl_down_sync(0xffffffffu, vd, off, 16);
        }
        if (c4 == 0) {
            g_esrc[base + ns + i] = vs;
            g_edst[base + ns + i] = vd;
        }
    }
}

// ---------------- fused GAT aggregation (warp per dst node, SINGLE PASS) -----
// out = (sum_j ex_j * h[src_j]) / (sum_j ex_j); normalization deferred, one
// loop over edges. Scores are O(1) so exp() needs no max-shift (max cancels).
// Each half-warp handles one edge per iteration. UNIFORM trip count across the
// whole warp (niter = ceil(cnt/2)) with a valid-predicate so every lane
// executes every __shfl_sync (R7 bug: divergent trip counts at odd degree).
template <bool RELU>
__global__ void gat_agg_kernel(const float* __restrict__ bias) {
    int w = (blockIdx.x * blockDim.x + threadIdx.x) >> 5;
    if (w >= NN) return;
    int lane = threadIdx.x & 31;
    int beg = g_rowptr[w], end = g_rowptr[w + 1];
    float ed = g_edst[w];

    int half = lane >> 4;       // 0 or 1: which edge of the pair
    int qc = (lane & 15) * 4;   // channel base (float4)
    bool leader = (lane & 15) == 0;
    int cnt = end - beg;
    int niter = (cnt + 1) >> 1; // uniform across warp

    float4 acc = make_float4(0.f, 0.f, 0.f, 0.f);
    float ssum = 0.f;           // accumulated on leader lanes only
    for (int t = 0; t < niter; t++) {
        int j = beg + 2 * t + half;
        bool valid = j < end;
        int jj = valid ? j : beg;           // safe index for the dead slot
        int sN = g_csr_src[jj];             // same addr across half: broadcast
        float a = 0.f;
        if (leader && valid) {
            float e = g_esrc[sN] + ed;
            e = e > 0.f ? e : NEG_SLOPE * e;
            a = __expf(e);
            ssum += a;
        }
        a = __shfl_sync(0xffffffffu, a, half << 4);   // a==0 for invalid slot
        float4 hv = *(const float4*)&g_h[(size_t)sN * HH + qc];
        acc.x += a * hv.x; acc.y += a * hv.y;
        acc.z += a * hv.z; acc.w += a * hv.w;
    }
    // total denom: leader lanes 0 and 16 hold the two partials
    float s0 = __shfl_sync(0xffffffffu, ssum, 0);
    float s1 = __shfl_sync(0xffffffffu, ssum, 16);
    float inv = 1.f / (s0 + s1);
    // cross-half channel reduce
    acc.x += __shfl_xor_sync(0xffffffffu, acc.x, 16);
    acc.y += __shfl_xor_sync(0xffffffffu, acc.y, 16);
    acc.z += __shfl_xor_sync(0xffffffffu, acc.z, 16);
    acc.w += __shfl_xor_sync(0xffffffffu, acc.w, 16);
    if (half == 0) {
        float4 bv = *(const float4*)&bias[qc];
        float4 v = make_float4(acc.x * inv + bv.x, acc.y * inv + bv.y,
                               acc.z * inv + bv.z, acc.w * inv + bv.w);
        if (RELU) {
            v.x = fmaxf(v.x, 0.f); v.y = fmaxf(v.y, 0.f);
            v.z = fmaxf(v.z, 0.f); v.w = fmaxf(v.w, 0.f);
        }
        *(float4*)&g_x2[(size_t)w * HH + qc] = v;
    }
}

// ---------------- pooling (batch is sorted: block per graph, no atomics) -----

__global__ void pool_kernel(const int* __restrict__ batch) {
    int b = blockIdx.x;
    int lo = 0, hi = NN;
    while (lo < hi) { int mid = (lo + hi) >> 1;
                      if (batch[mid] < b) lo = mid + 1; else hi = mid; }
    int start = lo;
    hi = NN;
    while (lo < hi) { int mid = (lo + hi) >> 1;
                      if (batch[mid] < b + 1) lo = mid + 1; else hi = mid; }
    int end = lo;

    int c = threadIdx.x & 63, r = threadIdx.x >> 6;   // 4 rows of 64
    float s = 0.f;
    for (int n = start + r; n < end; n += 4)
        s += g_x2[(size_t)n * HH + c];
    __shared__ float sm[4][HH];
    sm[r][c] = s;
    __syncthreads();
    if (threadIdx.x < HH) {
        float tot = sm[0][c] + sm[1][c] + sm[2][c] + sm[3][c];
        float cnt = (float)(end - start);
        g_pool[b * HH + c] = tot / fmaxf(cnt, 1.f);
    }
}

__global__ void final_linear_kernel(const float* __restrict__ Wlin,
                                    const float* __restrict__ blin,
                                    float* __restrict__ out) {
    int idx = blockIdx.x * blockDim.x + threadIdx.x;
    if (idx >= BB * CC) return;
    int b = idx / CC, j = idx % CC;
    float s = blin[j];
#pragma unroll
    for (int k = 0; k < HH; k++)
        s += g_pool[b * HH + k] * Wlin[j * HH + k];
    out[idx] = s;
}

// ---------------- launch -----------------------------------------------------

extern "C" void kernel_launch(void* const* d_in, const int* in_sizes, int n_in,
                              void* d_out, int out_size) {
    const float* x     = (const float*)d_in[0];
    const int*   ei    = (const int*)d_in[1];
    const int*   batch = (const int*)d_in[2];
    const float* W1 = (const float*)d_in[3];
    const float* as1 = (const float*)d_in[4];
    const float* ad1 = (const float*)d_in[5];
    const float* b1 = (const float*)d_in[6];
    const float* W2 = (const float*)d_in[7];
    const float* as2 = (const float*)d_in[8];
    const float* ad2 = (const float*)d_in[9];
    const float* b2 = (const float*)d_in[10];
    const float* W3 = (const float*)d_in[11];
    const float* as3 = (const float*)d_in[12];
    const float* ad3 = (const float*)d_in[13];
    const float* b3 = (const float*)d_in[14];
    const float* Wlin = (const float*)d_in[15];
    const float* blin = (const float*)d_in[16];

    cudaStream_t main_s = 0;
    cudaStream_t side;
    cudaStreamCreateWithFlags(&side, cudaStreamNonBlocking);
    cudaEvent_t evA, evB;
    cudaEventCreateWithFlags(&evA, cudaEventDisableTiming);
    cudaEventCreateWithFlags(&evB, cudaEventDisableTiming);

    // Fork: CSR build (depends only on edge_index) runs on `side`,
    // concurrently with the layer-1 GEMM (depends only on x, W1) on main.
    cudaEventRecord(evA, main_s);
    cudaStreamWaitEvent(side, evA, 0);
    csr_init_kernel<<<(NN + 255) / 256, 256, 0, side>>>();
    csr_hist_kernel<<<(EN + 255) / 256, 256, 0, side>>>(ei);
    scan1_kernel<<<NB_SCAN, SCAN_B, 0, side>>>();
    scan2_kernel<<<1, 256, 0, side>>>();
    scan3_kernel<<<(NN + 255) / 256, 256, 0, side>>>();
    csr_fill_kernel<<<(EN + 255) / 256, 256, 0, side>>>(ei);
    cudaEventRecord(evB, side);

    gemm_kernel<FIN, false><<<NN / 32, 128, 0, main_s>>>(x, W1, as1, ad1);

    // Join: aggregation needs both the CSR and the layer-1 GEMM results.
    cudaStreamWaitEvent(main_s, evB, 0);

    int ablocks = (NN * 32 + 255) / 256;
    gat_agg_kernel<true><<<ablocks, 256, 0, main_s>>>(b1);

    gemm_kernel<HH, true><<<NN / 32, 128, 0, main_s>>>(nullptr, W2, as2, ad2);
    gat_agg_kernel<true><<<ablocks, 256, 0, main_s>>>(b2);

    gemm_kernel<HH, true><<<NN / 32, 128, 0, main_s>>>(nullptr, W3, as3, ad3);
    gat_agg_kernel<false><<<ablocks, 256, 0, main_s>>>(b3);

    pool_kernel<<<BB, 256, 0, main_s>>>(batch);
    final_linear_kernel<<<(BB * CC + 127) / 128, 128, 0, main_s>>>(
        Wlin, blin, (float*)d_out);

    cudaEventDestroy(evA);
    cudaEventDestroy(evB);
    cudaStreamDestroy(side);
}

// round 9
// speedup vs baseline: 1.2426x; 1.2426x over previous
#include <cuda_runtime.h>
#include <cuda_fp16.h>

#define NN 100000
#define EE 1600000
#define EN 1700000   // EE + NN self loops
#define FIN 128
#define HH 64
#define BB 128
#define CC 10
#define NEG_SLOPE 0.2f

#define SCAN_B 512
#define NB_SCAN ((NN + SCAN_B - 1) / SCAN_B)   // 196

// ---------------- scratch (device globals; no runtime allocation) ------------
__device__ __half g_hh[NN * HH];   // W-transformed features (fp16, gather side)
__device__ float g_x2[NN * HH];    // layer output -> next layer input (fp32)
__device__ float g_esrc[NN];
__device__ float g_edst[NN];
__device__ int   g_deg[NN];
__device__ int   g_cursor[NN];
__device__ int   g_rowptr[NN + 1];
__device__ int   g_part[SCAN_B];
__device__ int   g_csr_src[EN];    // src node id per CSR slot (dst-sorted)
__device__ float g_ex[EN];         // per-edge exp(score) scratch
__device__ float g_pool[BB * HH];

// edge_index is int32 (JAX x64 disabled -> int64 silently becomes int32)
__device__ __forceinline__ void edge_sd(const int* __restrict__ ei, int i,
                                        int& s, int& d) {
    if (i < EE) { s = ei[i]; d = ei[EE + i]; }
    else        { s = i - EE; d = s; }   // self loops appended
}

// ---------------- CSR build --------------------------------------------------

__global__ void csr_init_kernel() {
    int i = blockIdx.x * blockDim.x + threadIdx.x;
    if (i < NN) g_deg[i] = 0;
}

__global__ void csr_hist_kernel(const int* __restrict__ ei) {
    int i = blockIdx.x * blockDim.x + threadIdx.x;
    if (i >= EN) return;
    int s, d; edge_sd(ei, i, s, d);
    atomicAdd(&g_deg[d], 1);
}

__global__ void scan1_kernel() {
    __shared__ int sm[SCAN_B];
    int t = threadIdx.x;
    int i = blockIdx.x * SCAN_B + t;
    int v = (i < NN) ? g_deg[i] : 0;
    sm[t] = v;
    __syncthreads();
    for (int off = 1; off < SCAN_B; off <<= 1) {
        int x = (t >= off) ? sm[t - off] : 0;
        __syncthreads();
        sm[t] += x;
        __syncthreads();
    }
    if (i < NN) g_rowptr[i] = sm[t] - v;          // exclusive within block
    if (t == SCAN_B - 1) g_part[blockIdx.x] = sm[t];
}

__global__ void scan2_kernel() {
    __shared__ int sm[256];
    int t = threadIdx.x;
    int v = (t < NB_SCAN) ? g_part[t] : 0;
    sm[t] = v;
    __syncthreads();
    for (int off = 1; off < 256; off <<= 1) {
        int x = (t >= off) ? sm[t - off] : 0;
        __syncthreads();
        sm[t] += x;
        __syncthreads();
    }
    if (t < NB_SCAN) g_part[t] = sm[t] - v;       // exclusive
}

__global__ void scan3_kernel() {
    int i = blockIdx.x * blockDim.x + threadIdx.x;
    if (i < NN) {
        int v = g_rowptr[i] + g_part[i / SCAN_B];
        g_rowptr[i] = v;
        g_cursor[i] = v;    // fill cursor starts at row base
    }
    if (i == 0) g_rowptr[NN] = EN;
}

__global__ void csr_fill_kernel(const int* __restrict__ ei) {
    int i = blockIdx.x * blockDim.x + threadIdx.x;
    if (i >= EN) return;
    int s, d; edge_sd(ei, i, s, d);
    int pos = atomicAdd(&g_cursor[d], 1);
    g_csr_src[pos] = s;
}

// ---------------- GEMM: h = in @ W^T (fp16 out), e_src/e_dst scores ----------
// 128 threads/block, 32 nodes/block. Each thread: 4 nodes x 4 channels.
// Scores computed from fp32 accumulators; h stored fp16 for the gather pass.
template <int FIN_T, bool FROM_X2>
__global__ void gemm_kernel(const float* __restrict__ in,
                            const float* __restrict__ W,
                            const float* __restrict__ a_src,
                            const float* __restrict__ a_dst) {
    __shared__ __align__(16) float ws[FIN_T * 64];
    __shared__ __align__(16) float xs[32][FIN_T];
    int tid = threadIdx.x;
    int c4 = tid & 15;       // channel quad id (channels c4*4 .. c4*4+3)
    int ng = tid >> 4;       // node group (4 nodes each)
    int base = blockIdx.x * 32;
    const float* srcp = FROM_X2 ? g_x2 : in;

    // load W coalesced, store swizzled: ws[k*64 + ((c/4 + k)&15)*4 + c%4]
    for (int idx = tid; idx < 64 * FIN_T; idx += 128) {
        int c = idx / FIN_T, k = idx - c * FIN_T;
        int q = c >> 2, r = c & 3;
        ws[k * 64 + (((q + k) & 15) << 2) + r] = W[idx];
    }
    // load x rows coalesced (float4)
    for (int idx = tid; idx < 32 * (FIN_T / 4); idx += 128) {
        int n = idx / (FIN_T / 4), kq = idx - n * (FIN_T / 4);
        ((float4*)xs[n])[kq] =
            ((const float4*)&srcp[(size_t)(base + n) * FIN_T])[kq];
    }
    __syncthreads();

    float4 acc0 = {0,0,0,0}, acc1 = {0,0,0,0}, acc2 = {0,0,0,0}, acc3 = {0,0,0,0};
    int ns = ng * 4;
#pragma unroll 4
    for (int k = 0; k < FIN_T; k += 4) {
        float4 x0 = *(const float4*)&xs[ns + 0][k];
        float4 x1 = *(const float4*)&xs[ns + 1][k];
        float4 x2 = *(const float4*)&xs[ns + 2][k];
        float4 x3 = *(const float4*)&xs[ns + 3][k];
        float4 w0 = *(const float4*)&ws[(k + 0) * 64 + (((c4 + k + 0) & 15) << 2)];
        float4 w1 = *(const float4*)&ws[(k + 1) * 64 + (((c4 + k + 1) & 15) << 2)];
        float4 w2 = *(const float4*)&ws[(k + 2) * 64 + (((c4 + k + 2) & 15) << 2)];
        float4 w3 = *(const float4*)&ws[(k + 3) * 64 + (((c4 + k + 3) & 15) << 2)];
#define FMA4(A, xv) \
        A.x += xv.x*w0.x + xv.y*w1.x + xv.z*w2.x + xv.w*w3.x; \
        A.y += xv.x*w0.y + xv.y*w1.y + xv.z*w2.y + xv.w*w3.y; \
        A.z += xv.x*w0.z + xv.y*w1.z + xv.z*w2.z + xv.w*w3.z; \
        A.w += xv.x*w0.w + xv.y*w1.w + xv.z*w2.w + xv.w*w3.w;
        FMA4(acc0, x0) FMA4(acc1, x1) FMA4(acc2, x2) FMA4(acc3, x3)
#undef FMA4
    }

    // write h as fp16 (8B per thread-node, coalesced across the 16 lanes)
    float4 accs[4] = {acc0, acc1, acc2, acc3};
#pragma unroll
    for (int i = 0; i < 4; i++) {
        __half2 h0 = __floats2half2_rn(accs[i].x, accs[i].y);
        __half2 h1 = __floats2half2_rn(accs[i].z, accs[i].w);
        *(__half2*)&g_hh[(size_t)(base + ns + i) * HH + c4 * 4 + 0] = h0;
        *(__half2*)&g_hh[(size_t)(base + ns + i) * HH + c4 * 4 + 2] = h1;
    }

    // per-node scores: dot over this thread's 4 channels, reduce over 16 lanes
    float4 as4 = *(const float4*)&a_src[c4 * 4];
    float4 ad4 = *(const float4*)&a_dst[c4 * 4];
#pragma unroll
    for (int i = 0; i < 4; i++) {
        float4 a = accs[i];
        float vs = a.x * as4.x + a.y * as4.y + a.z * as4.z + a.w * as4.w;
        float vd = a.x * ad4.x + a.y * ad4.y + a.z * ad4.z + a.w * ad4.w;
#pragma unroll
        for (int off = 8; off; off >>= 1) {
            vs += __shfl_down_sync(0xffffffffu, vs, off, 16);
            vd += __shfl_down_sync(0xffffffffu, vd, off, 16);
        }
        if (c4 == 0) {
            g_esrc[base + ns + i] = vs;
            g_edst[base + ns + i] = vd;
        }
    }
}

// ---------------- fused GAT aggregation (warp per dst node, TWO PASS) --------
// Scores are O(1) so exp() needs no max-shift (max cancels in alpha).
// pass1: gather scores, leaky-relu, ex=exp(e) stored, warp-sum.
// pass2: half-warp per edge, alpha = ex*inv, fp16 h-row gathers (8B/lane).
template <bool RELU>
__global__ void gat_agg_kernel(const float* __restrict__ bias) {
    int w = (blockIdx.x * blockDim.x + threadIdx.x) >> 5;
    if (w >= NN) return;
    int lane = threadIdx.x & 31;
    int beg = g_rowptr[w], end = g_rowptr[w + 1];
    float ed = g_edst[w];

    float ssum = 0.f;
    for (int j = beg + lane; j < end; j += 32) {
        float e = g_esrc[g_csr_src[j]] + ed;
        e = e > 0.f ? e : NEG_SLOPE * e;
        float ex = __expf(e);
        g_ex[j] = ex;
        ssum += ex;
    }
#pragma unroll
    for (int off = 16; off; off >>= 1)
        ssum += __shfl_xor_sync(0xffffffffu, ssum, off);
    float inv = 1.f / ssum;
    __syncwarp();

    int half = lane >> 4;       // 0 or 1: which edge of the pair
    int qc = (lane & 15) * 4;   // channel base (4 halves = 8 bytes)
    float4 acc = make_float4(0.f, 0.f, 0.f, 0.f);
    for (int j = beg + half; j < end; j += 2) {
        float a = g_ex[j] * inv;
        int sN = g_csr_src[j];
        uint2 u = *(const uint2*)&g_hh[(size_t)sN * HH + qc];
        float2 f0 = __half22float2(*(__half2*)&u.x);
        float2 f1 = __half22float2(*(__half2*)&u.y);
        acc.x += a * f0.x; acc.y += a * f0.y;
        acc.z += a * f1.x; acc.w += a * f1.y;
    }
    acc.x += __shfl_xor_sync(0xffffffffu, acc.x, 16);
    acc.y += __shfl_xor_sync(0xffffffffu, acc.y, 16);
    acc.z += __shfl_xor_sync(0xffffffffu, acc.z, 16);
    acc.w += __shfl_xor_sync(0xffffffffu, acc.w, 16);
    if (half == 0) {
        float4 bv = *(const float4*)&bias[qc];
        float4 v = make_float4(acc.x + bv.x, acc.y + bv.y,
                               acc.z + bv.z, acc.w + bv.w);
        if (RELU) {
            v.x = fmaxf(v.x, 0.f); v.y = fmaxf(v.y, 0.f);
            v.z = fmaxf(v.z, 0.f); v.w = fmaxf(v.w, 0.f);
        }
        *(float4*)&g_x2[(size_t)w * HH + qc] = v;
    }
}

// ---------------- pooling (batch is sorted: block per graph, no atomics) -----

__global__ void pool_kernel(const int* __restrict__ batch) {
    int b = blockIdx.x;
    int lo = 0, hi = NN;
    while (lo < hi) { int mid = (lo + hi) >> 1;
                      if (batch[mid] < b) lo = mid + 1; else hi = mid; }
    int start = lo;
    hi = NN;
    while (lo < hi) { int mid = (lo + hi) >> 1;
                      if (batch[mid] < b + 1) lo = mid + 1; else hi = mid; }
    int end = lo;

    int c = threadIdx.x & 63, r = threadIdx.x >> 6;   // 4 rows of 64
    float s = 0.f;
    for (int n = start + r; n < end; n += 4)
        s += g_x2[(size_t)n * HH + c];
    __shared__ float sm[4][HH];
    sm[r][c] = s;
    __syncthreads();
    if (threadIdx.x < HH) {
        float tot = sm[0][c] + sm[1][c] + sm[2][c] + sm[3][c];
        float cnt = (float)(end - start);
        g_pool[b * HH + c] = tot / fmaxf(cnt, 1.f);
    }
}

__global__ void final_linear_kernel(const float* __restrict__ Wlin,
                                    const float* __restrict__ blin,
                                    float* __restrict__ out) {
    int idx = blockIdx.x * blockDim.x + threadIdx.x;
    if (idx >= BB * CC) return;
    int b = idx / CC, j = idx % CC;
    float s = blin[j];
#pragma unroll
    for (int k = 0; k < HH; k++)
        s += g_pool[b * HH + k] * Wlin[j * HH + k];
    out[idx] = s;
}

// ---------------- launch -----------------------------------------------------

extern "C" void kernel_launch(void* const* d_in, const int* in_sizes, int n_in,
                              void* d_out, int out_size) {
    const float* x     = (const float*)d_in[0];
    const int*   ei    = (const int*)d_in[1];
    const int*   batch = (const int*)d_in[2];
    const float* W1 = (const float*)d_in[3];
    const float* as1 = (const float*)d_in[4];
    const float* ad1 = (const float*)d_in[5];
    const float* b1 = (const float*)d_in[6];
    const float* W2 = (const float*)d_in[7];
    const float* as2 = (const float*)d_in[8];
    const float* ad2 = (const float*)d_in[9];
    const float* b2 = (const float*)d_in[10];
    const float* W3 = (const float*)d_in[11];
    const float* as3 = (const float*)d_in[12];
    const float* ad3 = (const float*)d_in[13];
    const float* b3 = (const float*)d_in[14];
    const float* Wlin = (const float*)d_in[15];
    const float* blin = (const float*)d_in[16];

    cudaStream_t main_s = 0;
    cudaStream_t side;
    cudaStreamCreateWithFlags(&side, cudaStreamNonBlocking);
    cudaEvent_t evA, evB;
    cudaEventCreateWithFlags(&evA, cudaEventDisableTiming);
    cudaEventCreateWithFlags(&evB, cudaEventDisableTiming);

    // Fork: CSR build (depends only on edge_index) runs on `side`,
    // concurrently with the layer-1 GEMM (depends only on x, W1) on main.
    cudaEventRecord(evA, main_s);
    cudaStreamWaitEvent(side, evA, 0);
    csr_init_kernel<<<(NN + 255) / 256, 256, 0, side>>>();
    csr_hist_kernel<<<(EN + 255) / 256, 256, 0, side>>>(ei);
    scan1_kernel<<<NB_SCAN, SCAN_B, 0, side>>>();
    scan2_kernel<<<1, 256, 0, side>>>();
    scan3_kernel<<<(NN + 255) / 256, 256, 0, side>>>();
    csr_fill_kernel<<<(EN + 255) / 256, 256, 0, side>>>(ei);
    cudaEventRecord(evB, side);

    gemm_kernel<FIN, false><<<NN / 32, 128, 0, main_s>>>(x, W1, as1, ad1);

    // Join: aggregation needs both the CSR and the layer-1 GEMM results.
    cudaStreamWaitEvent(main_s, evB, 0);

    int ablocks = (NN * 32 + 255) / 256;
    gat_agg_kernel<true><<<ablocks, 256, 0, main_s>>>(b1);

    gemm_kernel<HH, true><<<NN / 32, 128, 0, main_s>>>(nullptr, W2, as2, ad2);
    gat_agg_kernel<true><<<ablocks, 256, 0, main_s>>>(b2);

    gemm_kernel<HH, true><<<NN / 32, 128, 0, main_s>>>(nullptr, W3, as3, ad3);
    gat_agg_kernel<false><<<ablocks, 256, 0, main_s>>>(b3);

    pool_kernel<<<BB, 256, 0, main_s>>>(batch);
    final_linear_kernel<<<(BB * CC + 127) / 128, 128, 0, main_s>>>(
        Wlin, blin, (float*)d_out);

    cudaEventDestroy(evA);
    cudaEventDestroy(evB);
    cudaStreamDestroy(side);
}